// round 1
// baseline (speedup 1.0000x reference)
#include <cuda_runtime.h>
#include <cstdint>
#include <cstddef>

// ---------------------------------------------------------------------------
// RankOneMoE: router (depth-2 gate, mean over S) + low-rank-MoE-augmented MLP.
// Strategy: everything as TF32 mma.sync GEMMs with explicit rna rounding.
//   gw[b,ek]  = (sum_s relu(x@gw1^T+b1g))[b,:]@gw2[ek,:]^T /512 + b2g[ek]
//   h         = relu([x | (x@SVH1^T)*gw] @ [W1^T ; U1] + b1m)
//   out       = [h | (h@SVH2^T)*gw] @ [W2^T ; U2] + b2m
// ---------------------------------------------------------------------------

#define BQ   16
#define SQ   512
#define HQ   768
#define FQ   3072
#define EQ   8
#define EKQ  128
#define G1Q  256
#define NTOK (BQ*SQ)      // 8192
#define LAMBDA 0.2f

// ---- scratch layout (single static device buffer, floats) ----
#define OFF_XC    0                         // 8192*768   tf32-rounded x
#define OFF_WG1   6291456                   // 256*768
#define OFF_SVH1  6488064                   // 128*768
#define OFF_W1    6586368                   // 3072*768
#define OFF_U1    8945664                   // 128*3072
#define OFF_SVH2  9338880                   // 128*3072
#define OFF_W2    9732096                   // 768*3072
#define OFF_U2    12091392                  // 128*768
#define OFF_G1    12189696                  // 8192*256
#define OFF_P     14286848                  // 16*256
#define OFF_GW    14290944                  // 16*128
#define OFF_B1M   14292992                  // 3072
#define OFF_B2M   14296064                  // 768
#define OFF_T1S   14296832                  // 8192*128
#define OFF_T2S   15345408                  // 8192*128
#define OFF_H     16393984                  // 8192*3072
#define SCRATCH_FLOATS 41559808

static __device__ __align__(256) float g_scratch[SCRATCH_FLOATS];

// ---- helpers ----
__device__ __forceinline__ float tf32r(float a) {
    float r;
    asm("cvt.rna.tf32.f32 %0, %1;" : "=f"(r) : "f"(a));
    return r;
}

__device__ __forceinline__ void mma8(float* c, const uint32_t* a, const uint32_t* b) {
    asm volatile(
        "mma.sync.aligned.m16n8k8.row.col.f32.tf32.tf32.f32 "
        "{%0,%1,%2,%3},{%4,%5,%6,%7},{%8,%9},{%0,%1,%2,%3};\n"
        : "+f"(c[0]), "+f"(c[1]), "+f"(c[2]), "+f"(c[3])
        : "r"(a[0]), "r"(a[1]), "r"(a[2]), "r"(a[3]), "r"(b[0]), "r"(b[1]));
}

// ---- elementwise rna-round copy ----
__global__ void k_cvt(float* __restrict__ dst, const float* __restrict__ src, int n4) {
    int i = blockIdx.x * blockDim.x + threadIdx.x;
    int stride = gridDim.x * blockDim.x;
    for (; i < n4; i += stride) {
        float4 v = reinterpret_cast<const float4*>(src)[i];
        v.x = tf32r(v.x); v.y = tf32r(v.y); v.z = tf32r(v.z); v.w = tf32r(v.w);
        reinterpret_cast<float4*>(dst)[i] = v;
    }
}

// ---- merged biases: b + lambda * sum_e TB[e,:] ----
__global__ void k_prep(const float* __restrict__ b1, const float* __restrict__ tb1,
                       const float* __restrict__ b2, const float* __restrict__ tb2,
                       float* __restrict__ b1m, float* __restrict__ b2m) {
    int i = blockIdx.x * blockDim.x + threadIdx.x;
    if (i < FQ) {
        float s = 0.f;
        #pragma unroll
        for (int e = 0; e < EQ; ++e) s += tb1[e * FQ + i];
        b1m[i] = b1[i] + LAMBDA * s;
    }
    if (i < HQ) {
        float s = 0.f;
        #pragma unroll
        for (int e = 0; e < EQ; ++e) s += tb2[e * HQ + i];
        b2m[i] = b2[i] + LAMBDA * s;
    }
}

// ---- P[b,g] = sum_s G1[b,s,g] ----
__global__ void k_sumG1(const float* __restrict__ G1, float* __restrict__ P) {
    int b = blockIdx.x;
    int g = threadIdx.x;           // 256 threads
    const float* p = G1 + (size_t)b * SQ * G1Q + g;
    float a = 0.f;
    #pragma unroll 8
    for (int s = 0; s < SQ; ++s) a += p[(size_t)s * G1Q];
    P[b * G1Q + g] = a;
}

// ---- gw[b,ek] = P[b,:] @ w2[ek,:]^T / S + b2g[ek] ----
__global__ void k_gwfin(const float* __restrict__ P, const float* __restrict__ w2,
                        const float* __restrict__ gb2, float* __restrict__ gw) {
    __shared__ float Ps[G1Q];
    int b = blockIdx.x, t = threadIdx.x;   // 128 threads
    Ps[t] = P[b * G1Q + t];
    Ps[t + 128] = P[b * G1Q + t + 128];
    __syncthreads();
    const float* w = w2 + t * G1Q;
    float a = 0.f;
    #pragma unroll 8
    for (int g = 0; g < G1Q; ++g) a += w[g] * Ps[g];
    gw[b * EKQ + t] = a * (1.0f / (float)SQ) + gb2[t];
}

// ---------------------------------------------------------------------------
// Generic TF32 GEMM:
//   D[M,N] = epi( A1[M,K1] @ B1[N,K1]^T  (+ A2[M,K2] @ B2[K2,N]) (+ bias) )
//   EPI: 0=none, 1=relu, 2=scale by gw[(row/512)*128 + col]
// ---------------------------------------------------------------------------
template<int BM, int BN, int WM, int WN, int EPI, bool HAS_A2, bool ROUND, bool HAS_BIAS>
__global__ void __launch_bounds__(WM * WN * 32)
k_gemm(const float* __restrict__ A1, const float* __restrict__ B1, int K1,
       const float* __restrict__ A2, const float* __restrict__ B2, int K2,
       const float* __restrict__ bias, const float* __restrict__ gw,
       float* __restrict__ D, int M, int N) {
    constexpr int THREADS = WM * WN * 32;
    constexpr int BK = 16;
    constexpr int WTM = BM / WM, WTN = BN / WN;
    constexpr int MT = WTM / 16, NT = WTN / 8;
    constexpr int LDA = BM + 8, LDB = BN + 8;     // stride % 32 == 8 -> conflict-free frag loads
    constexpr int LAI = (BM * BK / 4) / THREADS;  // float4 per thread (A)
    constexpr int LBI = (BN * BK / 4) / THREADS;  // float4 per thread (B)

    __shared__ __align__(16) float As[2][BK][LDA];
    __shared__ __align__(16) float Bs[2][BK][LDB];

    const int tid = threadIdx.x;
    const int wid = tid >> 5, lane = tid & 31;
    const int gid = lane >> 2, tig = lane & 3;
    const int wm = (wid / WN) * WTM;
    const int wn = (wid % WN) * WTN;
    const int bM = blockIdx.y * BM;
    const int bN = blockIdx.x * BN;

    float acc[MT][NT][4];
    #pragma unroll
    for (int mi = 0; mi < MT; ++mi)
        #pragma unroll
        for (int ni = 0; ni < NT; ++ni)
            #pragma unroll
            for (int j = 0; j < 4; ++j) acc[mi][ni][j] = 0.f;

    const int T1 = K1 / BK;
    const int T2 = HAS_A2 ? (K2 / BK) : 0;
    const int T = T1 + T2;

    float4 ra[LAI], rb[LBI];

    auto loadg = [&](int kt) {
        if (!HAS_A2 || kt < T1) {
            const int k0 = kt * BK;
            #pragma unroll
            for (int i = 0; i < LAI; ++i) {
                int idx = tid + i * THREADS, r = idx >> 2, c = idx & 3;
                ra[i] = *reinterpret_cast<const float4*>(A1 + (size_t)(bM + r) * K1 + k0 + c * 4);
            }
            #pragma unroll
            for (int i = 0; i < LBI; ++i) {
                int idx = tid + i * THREADS, r = idx >> 2, c = idx & 3;
                rb[i] = *reinterpret_cast<const float4*>(B1 + (size_t)(bN + r) * K1 + k0 + c * 4);
            }
        } else {
            const int k0 = (kt - T1) * BK;
            #pragma unroll
            for (int i = 0; i < LAI; ++i) {
                int idx = tid + i * THREADS, r = idx >> 2, c = idx & 3;
                ra[i] = *reinterpret_cast<const float4*>(A2 + (size_t)(bM + r) * K2 + k0 + c * 4);
            }
            #pragma unroll
            for (int i = 0; i < LBI; ++i) {
                int idx = tid + i * THREADS;
                int rk = idx / (BN / 4), cg = idx % (BN / 4);
                rb[i] = *reinterpret_cast<const float4*>(B2 + (size_t)(k0 + rk) * N + bN + cg * 4);
            }
        }
    };

    auto stores = [&](int buf, bool phase2) {
        #pragma unroll
        for (int i = 0; i < LAI; ++i) {
            int idx = tid + i * THREADS, r = idx >> 2, c = idx & 3;
            As[buf][c * 4 + 0][r] = ra[i].x;
            As[buf][c * 4 + 1][r] = ra[i].y;
            As[buf][c * 4 + 2][r] = ra[i].z;
            As[buf][c * 4 + 3][r] = ra[i].w;
        }
        if (!phase2) {
            #pragma unroll
            for (int i = 0; i < LBI; ++i) {
                int idx = tid + i * THREADS, r = idx >> 2, c = idx & 3;
                Bs[buf][c * 4 + 0][r] = rb[i].x;
                Bs[buf][c * 4 + 1][r] = rb[i].y;
                Bs[buf][c * 4 + 2][r] = rb[i].z;
                Bs[buf][c * 4 + 3][r] = rb[i].w;
            }
        } else {
            #pragma unroll
            for (int i = 0; i < LBI; ++i) {
                int idx = tid + i * THREADS;
                int rk = idx / (BN / 4), cg = idx % (BN / 4);
                *reinterpret_cast<float4*>(&Bs[buf][rk][cg * 4]) = rb[i];
            }
        }
    };

    loadg(0);
    stores(0, false);
    __syncthreads();

    for (int t = 0; t < T; ++t) {
        if (t + 1 < T) loadg(t + 1);
        const int buf = t & 1;
        #pragma unroll
        for (int kk = 0; kk < 2; ++kk) {
            const int k8 = kk * 8;
            uint32_t af[MT][4], bf[NT][2];
            #pragma unroll
            for (int mi = 0; mi < MT; ++mi) {
                int mr = wm + mi * 16 + gid;
                af[mi][0] = __float_as_uint(As[buf][k8 + tig][mr]);
                af[mi][1] = __float_as_uint(As[buf][k8 + tig][mr + 8]);
                af[mi][2] = __float_as_uint(As[buf][k8 + tig + 4][mr]);
                af[mi][3] = __float_as_uint(As[buf][k8 + tig + 4][mr + 8]);
            }
            #pragma unroll
            for (int ni = 0; ni < NT; ++ni) {
                int nc = wn + ni * 8 + gid;
                bf[ni][0] = __float_as_uint(Bs[buf][k8 + tig][nc]);
                bf[ni][1] = __float_as_uint(Bs[buf][k8 + tig + 4][nc]);
            }
            #pragma unroll
            for (int mi = 0; mi < MT; ++mi)
                #pragma unroll
                for (int ni = 0; ni < NT; ++ni)
                    mma8(acc[mi][ni], af[mi], bf[ni]);
        }
        if (t + 1 < T) {
            stores((t + 1) & 1, (t + 1) >= T1);
            __syncthreads();
        }
    }

    // epilogue
    #pragma unroll
    for (int mi = 0; mi < MT; ++mi) {
        const int r0 = bM + wm + mi * 16 + gid;
        #pragma unroll
        for (int ni = 0; ni < NT; ++ni) {
            const int c0 = bN + wn + ni * 8 + tig * 2;
            float bias0 = 0.f, bias1 = 0.f;
            if (HAS_BIAS) { bias0 = bias[c0]; bias1 = bias[c0 + 1]; }
            #pragma unroll
            for (int h = 0; h < 2; ++h) {
                const int r = r0 + h * 8;
                float v0 = acc[mi][ni][2 * h + 0];
                float v1 = acc[mi][ni][2 * h + 1];
                if (HAS_BIAS) { v0 += bias0; v1 += bias1; }
                if (EPI == 1) { v0 = fmaxf(v0, 0.f); v1 = fmaxf(v1, 0.f); }
                if (EPI == 2) {
                    const int bb = (r >> 9) * EKQ;
                    v0 *= gw[bb + c0];
                    v1 *= gw[bb + c0 + 1];
                }
                if (ROUND) { v0 = tf32r(v0); v1 = tf32r(v1); }
                *reinterpret_cast<float2*>(D + (size_t)r * N + c0) = make_float2(v0, v1);
            }
        }
    }
}

// ---------------------------------------------------------------------------
extern "C" void kernel_launch(void* const* d_in, const int* in_sizes, int n_in,
                              void* d_out, int out_size) {
    const float* x       = (const float*)d_in[0];
    const float* gate_w1 = (const float*)d_in[1];
    const float* gate_b1 = (const float*)d_in[2];
    const float* gate_w2 = (const float*)d_in[3];
    const float* gate_b2 = (const float*)d_in[4];
    const float* W1      = (const float*)d_in[5];
    const float* b1      = (const float*)d_in[6];
    const float* W2      = (const float*)d_in[7];
    const float* b2      = (const float*)d_in[8];
    const float* U1      = (const float*)d_in[9];
    const float* SVH1    = (const float*)d_in[10];
    const float* U2      = (const float*)d_in[11];
    const float* SVH2    = (const float*)d_in[12];
    const float* TB1     = (const float*)d_in[13];
    const float* TB2     = (const float*)d_in[14];
    float* out = (float*)d_out;

    float* S = nullptr;
    cudaGetSymbolAddress((void**)&S, g_scratch);
    float* xc   = S + OFF_XC;
    float* wg1  = S + OFF_WG1;
    float* svh1 = S + OFF_SVH1;
    float* w1c  = S + OFF_W1;
    float* u1   = S + OFF_U1;
    float* svh2 = S + OFF_SVH2;
    float* w2c  = S + OFF_W2;
    float* u2   = S + OFF_U2;
    float* G1   = S + OFF_G1;
    float* P    = S + OFF_P;
    float* gw   = S + OFF_GW;
    float* b1m  = S + OFF_B1M;
    float* b2m  = S + OFF_B2M;
    float* t1s  = S + OFF_T1S;
    float* t2s  = S + OFF_T2S;
    float* hbuf = S + OFF_H;

    // 1) pre-round all TF32 GEMM operands (rna, unbiased)
    k_cvt<<<256, 256>>>(xc,   x,       NTOK * HQ / 4);
    k_cvt<<<64,  256>>>(wg1,  gate_w1, G1Q * HQ / 4);
    k_cvt<<<32,  256>>>(svh1, SVH1,    EKQ * HQ / 4);
    k_cvt<<<128, 256>>>(w1c,  W1,      FQ * HQ / 4);
    k_cvt<<<64,  256>>>(u1,   U1,      EKQ * FQ / 4);
    k_cvt<<<64,  256>>>(svh2, SVH2,    EKQ * FQ / 4);
    k_cvt<<<128, 256>>>(w2c,  W2,      HQ * FQ / 4);
    k_cvt<<<32,  256>>>(u2,   U2,      EKQ * HQ / 4);
    k_prep<<<(FQ + 255) / 256, 256>>>(b1, TB1, b2, TB2, b1m, b2m);

    // 2) router: G1 = relu(x @ gate_w1^T + gate_b1)   [8192,256]
    k_gemm<128, 128, 2, 4, 1, false, false, true>
        <<<dim3(G1Q / 128, NTOK / 128), 256>>>(
            xc, wg1, HQ, nullptr, nullptr, 0, gate_b1, nullptr, G1, NTOK, G1Q);

    // 3) gw = (sum_s G1) @ w2^T / S + b2g   (mean commutes with linear layer)
    k_sumG1<<<BQ, 256>>>(G1, P);
    k_gwfin<<<BQ, 128>>>(P, gate_w2, gate_b2, gw);

    // 4) t1s = (x @ SVH1^T) * gw   [8192,128], rounded
    k_gemm<64, 64, 2, 2, 2, false, true, false>
        <<<dim3(EKQ / 64, NTOK / 64), 128>>>(
            xc, svh1, HQ, nullptr, nullptr, 0, nullptr, gw, t1s, NTOK, EKQ);

    // 5) h = relu(x @ W1^T + t1s @ U1 + b1m)   [8192,3072], rounded
    k_gemm<128, 128, 2, 4, 1, true, true, true>
        <<<dim3(FQ / 128, NTOK / 128), 256>>>(
            xc, w1c, HQ, t1s, u1, EKQ, b1m, nullptr, hbuf, NTOK, FQ);

    // 6) t2s = (h @ SVH2^T) * gw   [8192,128], rounded
    k_gemm<64, 64, 2, 2, 2, false, true, false>
        <<<dim3(EKQ / 64, NTOK / 64), 128>>>(
            hbuf, svh2, FQ, nullptr, nullptr, 0, nullptr, gw, t2s, NTOK, EKQ);

    // 7) out = h @ W2^T + t2s @ U2 + b2m   [8192,768]
    k_gemm<128, 128, 2, 4, 0, true, false, true>
        <<<dim3(HQ / 128, NTOK / 128), 256>>>(
            hbuf, w2c, FQ, t2s, u2, EKQ, b2m, nullptr, out, NTOK, HQ);
}

// round 3
// speedup vs baseline: 1.1150x; 1.1150x over previous
#include <cuda_runtime.h>
#include <cstdint>
#include <cstddef>

// ---------------------------------------------------------------------------
// RankOneMoE, legacy tensor path (mma.sync.m16n8k8.tf32 — the harness PTX
// target is compute_103 without the 'a' feature set, so tcgen05 is out).
//   gw[b,ek]  = (sum_s relu(x@gw1^T+b1g))[b,:]@gw2[ek,:]^T /512 + b2g[ek]
//   h         = relu([x | (x@SVH1^T)*gw] @ [W1^T ; U1] + b1m)
//   out       = [h | (h@SVH2^T)*gw] @ [W2^T ; U2] + b2m
// All MMA operands pre-rounded to tf32 (rna) and stored in a k-interleaved
// layout so fragment loads are single LDS.128.
// ---------------------------------------------------------------------------

#define BQ   16
#define SQ   512
#define HQ   768
#define FQ   3072
#define EQ   8
#define EKQ  128
#define G1Q  256
#define NTOK (BQ*SQ)      // 8192
#define LAMBDA 0.2f

// ---- scratch layout (floats) ----
#define OFF_XC    0                         // 8192*768
#define OFF_WG1   6291456                   // 256*768
#define OFF_SVH1  6488064                   // 128*768
#define OFF_W1    6586368                   // 3072*768
#define OFF_U1T   8945664                   // 3072*128
#define OFF_SVH2  9338880                   // 128*3072
#define OFF_W2    9732096                   // 768*3072
#define OFF_U2T   12091392                  // 768*128
#define OFF_G1    12189696                  // 8192*256
#define OFF_GW    14290944                  // 16*128
#define OFF_B1M   14292992                  // 3072
#define OFF_B2M   14296064                  // 768
#define OFF_T1S   14296832                  // 8192*128  (also temp P8 before t1s)
#define OFF_T2S   15345408                  // 8192*128
#define OFF_H     16393984                  // 8192*3072
#define SCRATCH_FLOATS 41559808

static __device__ __align__(256) float g_scratch[SCRATCH_FLOATS];

// ---------------------------- helpers --------------------------------------
__device__ __forceinline__ float tf32r(float a) {
    float r;
    asm("cvt.rna.tf32.f32 %0, %1;" : "=f"(r) : "f"(a));
    return r;
}
__device__ __forceinline__ uint32_t s2u(const void* p) {
    uint32_t a;
    asm("{ .reg .u64 t; cvta.to.shared.u64 t, %1; cvt.u32.u64 %0, t; }" : "=r"(a) : "l"(p));
    return a;
}
// interleave within 16-col group: r -> (r%4)*4 + r/4   (involution)
__device__ __forceinline__ int ilv16(int c) {
    return (c & ~15) | ((c & 3) << 2) | ((c >> 2) & 3);
}
__device__ __forceinline__ void mma8(float* c,
                                     uint32_t a0, uint32_t a1, uint32_t a2, uint32_t a3,
                                     uint32_t b0, uint32_t b1) {
    asm volatile(
        "mma.sync.aligned.m16n8k8.row.col.f32.tf32.tf32.f32 "
        "{%0,%1,%2,%3},{%4,%5,%6,%7},{%8,%9},{%0,%1,%2,%3};\n"
        : "+f"(c[0]), "+f"(c[1]), "+f"(c[2]), "+f"(c[3])
        : "r"(a0), "r"(a1), "r"(a2), "r"(a3), "r"(b0), "r"(b1));
}

// ---------------------------- pack kernels ---------------------------------
// round to tf32 + k-interleave each 16-col group (C % 16 == 0)
__global__ void k_pack(float* __restrict__ dst, const float* __restrict__ src, int ngroups) {
    int g = blockIdx.x * blockDim.x + threadIdx.x;
    if (g >= ngroups) return;
    const float4* s = reinterpret_cast<const float4*>(src) + (size_t)g * 4;
    float4 v0 = s[0], v1 = s[1], v2 = s[2], v3 = s[3];
    float4* d = reinterpret_cast<float4*>(dst) + (size_t)g * 4;
    d[0] = make_float4(tf32r(v0.x), tf32r(v1.x), tf32r(v2.x), tf32r(v3.x));
    d[1] = make_float4(tf32r(v0.y), tf32r(v1.y), tf32r(v2.y), tf32r(v3.y));
    d[2] = make_float4(tf32r(v0.z), tf32r(v1.z), tf32r(v2.z), tf32r(v3.z));
    d[3] = make_float4(tf32r(v0.w), tf32r(v1.w), tf32r(v2.w), tf32r(v3.w));
}

// transpose src[128, Ncols] -> dst[Ncols, 128] with round + interleave
__global__ void k_tr_ilv(const float* __restrict__ S_, float* __restrict__ Dst, int Ncols) {
    __shared__ float t[32][33];
    const int nx = blockIdx.x * 32, my = blockIdx.y * 32;
    const int x = threadIdx.x, y = threadIdx.y;
    #pragma unroll
    for (int i = 0; i < 32; i += 8)
        t[y + i][x] = S_[(size_t)(my + y + i) * Ncols + nx + x];
    __syncthreads();
    #pragma unroll
    for (int i = 0; i < 32; i += 8)
        Dst[(size_t)(nx + y + i) * 128 + ilv16(my + x)] = tf32r(t[x][y + i]);
}

__global__ void k_prep(const float* __restrict__ b1, const float* __restrict__ tb1,
                       const float* __restrict__ b2, const float* __restrict__ tb2,
                       float* __restrict__ b1m, float* __restrict__ b2m) {
    int i = blockIdx.x * blockDim.x + threadIdx.x;
    if (i < FQ) {
        float s = 0.f;
        #pragma unroll
        for (int e = 0; e < EQ; ++e) s += tb1[e * FQ + i];
        b1m[i] = b1[i] + LAMBDA * s;
    }
    if (i < HQ) {
        float s = 0.f;
        #pragma unroll
        for (int e = 0; e < EQ; ++e) s += tb2[e * HQ + i];
        b2m[i] = b2[i] + LAMBDA * s;
    }
}

// two-level mean reduction over S
__global__ void k_sumG1b(const float* __restrict__ G1, float* __restrict__ P8) {
    int b = blockIdx.x, ch = blockIdx.y, g = threadIdx.x;      // 256 threads
    const float* p = G1 + ((size_t)b * SQ + ch * 64) * G1Q + g;
    float a = 0.f;
    #pragma unroll 8
    for (int s = 0; s < 64; ++s) a += p[(size_t)s * G1Q];
    P8[(b * 8 + ch) * G1Q + g] = a;
}

__global__ void k_gwfin(const float* __restrict__ P8, const float* __restrict__ w2,
                        const float* __restrict__ gb2, float* __restrict__ gw) {
    __shared__ float Ps[G1Q];
    int b = blockIdx.x, t = threadIdx.x;   // 128 threads
    #pragma unroll
    for (int half = 0; half < 2; ++half) {
        int col = t + half * 128;
        float a = 0.f;
        #pragma unroll
        for (int ch = 0; ch < 8; ++ch) a += P8[(b * 8 + ch) * G1Q + col];
        Ps[col] = a;
    }
    __syncthreads();
    const float* w = w2 + (size_t)t * G1Q;
    float a = 0.f;
    #pragma unroll 8
    for (int g = 0; g < G1Q; ++g) a += w[g] * Ps[g];
    gw[b * EKQ + t] = a * (1.0f / (float)SQ) + gb2[t];
}

// ---------------------------------------------------------------------------
// Pipelined TF32 mma.sync GEMM on interleaved operands.
//   D[8192,N] = epi( A1[8192,K1] @ B1[N,K1]^T (+ A2[8192,K2] @ B2[N,K2]^T) )
//   4-stage cp.async, BK=16, warp tiles WTMxWTN, fragments via LDS.128.
//   EPI: 0=none, 1=relu, 2=scale by gw[(row/512)*128 + col]
// ---------------------------------------------------------------------------
template<int BM, int BN, int WM, int WN, int EPI,
         bool HAS2, bool ROUND, bool HAS_BIAS, bool ILVOUT>
__global__ void __launch_bounds__(WM * WN * 32)
k_mma(const float* __restrict__ A1, const float* __restrict__ B1, int K1,
      const float* __restrict__ A2, const float* __restrict__ B2, int K2,
      const float* __restrict__ bias, const float* __restrict__ gw,
      float* __restrict__ D, int N)
{
    constexpr int THREADS = WM * WN * 32;
    constexpr int WTM = BM / WM, WTN = BN / WN;
    constexpr int MT = WTM / 16, NT = WTN / 8;
    constexpr int STGF = (BM + BN) * 16;          // floats per stage
    constexpr int AIT = (BM * 4) / THREADS;       // cp.async chunks per thread (A)
    constexpr int BIT = (BN * 4) / THREADS;

    extern __shared__ float sm[];
    const uint32_t smb = s2u(sm);

    const int tid = threadIdx.x;
    const int wid = tid >> 5, lane = tid & 31;
    const int gid = lane >> 2, tig = lane & 3;
    const int wm = (wid / WN) * WTM;
    const int wn = (wid % WN) * WTN;
    const int bM = blockIdx.y * BM;
    const int bN = blockIdx.x * BN;
    const int T1 = K1 >> 4;
    const int T  = T1 + (HAS2 ? (K2 >> 4) : 0);

    float acc[MT][NT][4];
    #pragma unroll
    for (int mi = 0; mi < MT; ++mi)
        #pragma unroll
        for (int ni = 0; ni < NT; ++ni)
            #pragma unroll
            for (int j = 0; j < 4; ++j) acc[mi][ni][j] = 0.f;

    auto issue = [&](int jj) {
        const float* a; const float* b; int lda, ldb, k0;
        if (!HAS2 || jj < T1) { a = A1; lda = K1; b = B1; ldb = K1; k0 = jj << 4; }
        else                  { a = A2; lda = K2; b = B2; ldb = K2; k0 = (jj - T1) << 4; }
        const uint32_t sA = smb + (uint32_t)((jj & 3) * STGF) * 4u;
        const uint32_t sB = sA + (uint32_t)BM * 64u;
        #pragma unroll
        for (int i = 0; i < AIT; ++i) {
            int idx = tid + i * THREADS; int r = idx >> 2, c = idx & 3;
            const float* src = a + (size_t)(bM + r) * lda + k0 + c * 4;
            asm volatile("cp.async.cg.shared.global [%0], [%1], 16;\n"
                         :: "r"(sA + (uint32_t)(r * 64 + c * 16)), "l"(src) : "memory");
        }
        #pragma unroll
        for (int i = 0; i < BIT; ++i) {
            int idx = tid + i * THREADS; int r = idx >> 2, c = idx & 3;
            const float* src = b + (size_t)(bN + r) * ldb + k0 + c * 4;
            asm volatile("cp.async.cg.shared.global [%0], [%1], 16;\n"
                         :: "r"(sB + (uint32_t)(r * 64 + c * 16)), "l"(src) : "memory");
        }
    };

    issue(0); asm volatile("cp.async.commit_group;\n" ::: "memory");
    issue(1); asm volatile("cp.async.commit_group;\n" ::: "memory");
    issue(2); asm volatile("cp.async.commit_group;\n" ::: "memory");

    for (int j = 0; j < T; ++j) {
        asm volatile("cp.async.wait_group 2;\n" ::: "memory");
        __syncthreads();

        const float* sA = sm + (j & 3) * STGF;
        const float* sB = sA + BM * 16;

        float4 fa[MT][2]; float4 fb[NT];
        #pragma unroll
        for (int mi = 0; mi < MT; ++mi) {
            const int r = wm + mi * 16 + gid;
            fa[mi][0] = *reinterpret_cast<const float4*>(sA + r * 16 + tig * 4);
            fa[mi][1] = *reinterpret_cast<const float4*>(sA + (r + 8) * 16 + tig * 4);
        }
        #pragma unroll
        for (int ni = 0; ni < NT; ++ni) {
            const int c = wn + ni * 8 + gid;
            fb[ni] = *reinterpret_cast<const float4*>(sB + c * 16 + tig * 4);
        }

        if (j + 3 < T) issue(j + 3);                      // refills slot (j-1)&3
        asm volatile("cp.async.commit_group;\n" ::: "memory");

        #pragma unroll
        for (int mi = 0; mi < MT; ++mi)
            #pragma unroll
            for (int ni = 0; ni < NT; ++ni)
                mma8(acc[mi][ni],
                     __float_as_uint(fa[mi][0].x), __float_as_uint(fa[mi][1].x),
                     __float_as_uint(fa[mi][0].y), __float_as_uint(fa[mi][1].y),
                     __float_as_uint(fb[ni].x),    __float_as_uint(fb[ni].y));
        #pragma unroll
        for (int mi = 0; mi < MT; ++mi)
            #pragma unroll
            for (int ni = 0; ni < NT; ++ni)
                mma8(acc[mi][ni],
                     __float_as_uint(fa[mi][0].z), __float_as_uint(fa[mi][1].z),
                     __float_as_uint(fa[mi][0].w), __float_as_uint(fa[mi][1].w),
                     __float_as_uint(fb[ni].z),    __float_as_uint(fb[ni].w));
    }

    // epilogue
    #pragma unroll
    for (int mi = 0; mi < MT; ++mi) {
        const int r0 = bM + wm + mi * 16 + gid;
        #pragma unroll
        for (int ni = 0; ni < NT; ++ni) {
            const int c = bN + wn + ni * 8 + tig * 2;
            const float bb0 = HAS_BIAS ? bias[c] : 0.f;
            const float bb1 = HAS_BIAS ? bias[c + 1] : 0.f;
            #pragma unroll
            for (int h = 0; h < 2; ++h) {
                const int r = r0 + h * 8;
                float v0 = acc[mi][ni][2 * h + 0] + bb0;
                float v1 = acc[mi][ni][2 * h + 1] + bb1;
                if (EPI == 1) { v0 = fmaxf(v0, 0.f); v1 = fmaxf(v1, 0.f); }
                if (EPI == 2) {
                    const int gb = (r >> 9) << 7;
                    v0 *= gw[gb + c]; v1 *= gw[gb + c + 1];
                }
                if (ROUND) { v0 = tf32r(v0); v1 = tf32r(v1); }
                if (ILVOUT) {
                    D[(size_t)r * N + ilv16(c)]     = v0;
                    D[(size_t)r * N + ilv16(c + 1)] = v1;
                } else {
                    *reinterpret_cast<float2*>(D + (size_t)r * N + c) = make_float2(v0, v1);
                }
            }
        }
    }
}

// ---------------------------------------------------------------------------
extern "C" void kernel_launch(void* const* d_in, const int* in_sizes, int n_in,
                              void* d_out, int out_size) {
    const float* x       = (const float*)d_in[0];
    const float* gate_w1 = (const float*)d_in[1];
    const float* gate_b1 = (const float*)d_in[2];
    const float* gate_w2 = (const float*)d_in[3];
    const float* gate_b2 = (const float*)d_in[4];
    const float* W1      = (const float*)d_in[5];
    const float* b1      = (const float*)d_in[6];
    const float* W2      = (const float*)d_in[7];
    const float* b2      = (const float*)d_in[8];
    const float* U1      = (const float*)d_in[9];
    const float* SVH1    = (const float*)d_in[10];
    const float* U2      = (const float*)d_in[11];
    const float* SVH2    = (const float*)d_in[12];
    const float* TB1     = (const float*)d_in[13];
    const float* TB2     = (const float*)d_in[14];
    float* out = (float*)d_out;

    float* S = nullptr;
    cudaGetSymbolAddress((void**)&S, g_scratch);
    float* xc    = S + OFF_XC;
    float* wg1c  = S + OFF_WG1;
    float* svh1c = S + OFF_SVH1;
    float* w1c   = S + OFF_W1;
    float* u1t   = S + OFF_U1T;
    float* svh2c = S + OFF_SVH2;
    float* w2c   = S + OFF_W2;
    float* u2t   = S + OFF_U2T;
    float* G1    = S + OFF_G1;
    float* gwv   = S + OFF_GW;
    float* b1m   = S + OFF_B1M;
    float* b2m   = S + OFF_B2M;
    float* t1s   = S + OFF_T1S;
    float* t2s   = S + OFF_T2S;
    float* hbuf  = S + OFF_H;
    float* P8    = S + OFF_T1S;        // temp, consumed before t1s is written

    // router: BM64 BN256, 4 warps (1x4) of 64x64
    auto kr = k_mma<64, 256, 1, 4, 1, false, false, true, false>;
    // t-GEMMs: BM64 BN128, 4 warps (2x2) of 32x64
    auto kt = k_mma<64, 128, 2, 2, 2, false, true, false, true>;
    // fc1: BM128 BN256, 8 warps (2x4) of 64x64
    auto k1 = k_mma<128, 256, 2, 4, 1, true, true, true, true>;
    // fc2: same tiles, plain epilogue
    auto k2 = k_mma<128, 256, 2, 4, 0, true, false, true, false>;

    const int SM_R = 4 * (64 + 256) * 16 * 4;      // 81920
    const int SM_T = 4 * (64 + 128) * 16 * 4;      // 49152
    const int SM_F = 4 * (128 + 256) * 16 * 4;     // 98304
    cudaFuncSetAttribute((const void*)kr, cudaFuncAttributeMaxDynamicSharedMemorySize, SM_R);
    cudaFuncSetAttribute((const void*)kt, cudaFuncAttributeMaxDynamicSharedMemorySize, SM_T);
    cudaFuncSetAttribute((const void*)k1, cudaFuncAttributeMaxDynamicSharedMemorySize, SM_F);
    cudaFuncSetAttribute((const void*)k2, cudaFuncAttributeMaxDynamicSharedMemorySize, SM_F);

    // 1) round + interleave all MMA operands
    k_pack<<<(NTOK * HQ / 16 + 255) / 256, 256>>>(xc,    x,       NTOK * HQ / 16);
    k_pack<<<(G1Q * HQ / 16 + 255) / 256, 256>>>(wg1c,  gate_w1, G1Q * HQ / 16);
    k_pack<<<(EKQ * HQ / 16 + 255) / 256, 256>>>(svh1c, SVH1,    EKQ * HQ / 16);
    k_pack<<<(FQ * HQ / 16 + 255) / 256, 256>>>(w1c,   W1,      FQ * HQ / 16);
    k_pack<<<(EKQ * FQ / 16 + 255) / 256, 256>>>(svh2c, SVH2,    EKQ * FQ / 16);
    k_pack<<<(HQ * FQ / 16 + 255) / 256, 256>>>(w2c,   W2,      HQ * FQ / 16);
    k_tr_ilv<<<dim3(FQ / 32, 4), dim3(32, 8)>>>(U1, u1t, FQ);
    k_tr_ilv<<<dim3(HQ / 32, 4), dim3(32, 8)>>>(U2, u2t, HQ);
    k_prep<<<(FQ + 255) / 256, 256>>>(b1, TB1, b2, TB2, b1m, b2m);

    // 2) router: G1 = relu(x @ gate_w1^T + gate_b1)   [8192,256] plain
    kr<<<dim3(1, NTOK / 64), 128, SM_R>>>(
        xc, wg1c, HQ, nullptr, nullptr, 0, gate_b1, nullptr, G1, G1Q);

    // 3) gw = mean_s(G1) @ gate_w2^T + gate_b2  (mean commutes with linear)
    k_sumG1b<<<dim3(BQ, 8), 256>>>(G1, P8);
    k_gwfin<<<BQ, 128>>>(P8, gate_w2, gate_b2, gwv);

    // 4) t1s = round((x @ SVH1^T) * gw)   [8192,128] ILV
    kt<<<dim3(1, NTOK / 64), 128, SM_T>>>(
        xc, svh1c, HQ, nullptr, nullptr, 0, nullptr, gwv, t1s, EKQ);

    // 5) h = round(relu(x @ W1^T + t1s @ U1 + b1m))   [8192,3072] ILV
    k1<<<dim3(FQ / 256, NTOK / 128), 256, SM_F>>>(
        xc, w1c, HQ, t1s, u1t, EKQ, b1m, nullptr, hbuf, FQ);

    // 6) t2s = round((h @ SVH2^T) * gw)   [8192,128] ILV
    kt<<<dim3(1, NTOK / 64), 128, SM_T>>>(
        hbuf, svh2c, FQ, nullptr, nullptr, 0, nullptr, gwv, t2s, EKQ);

    // 7) out = h @ W2^T + t2s @ U2 + b2m   [8192,768] plain
    k2<<<dim3(HQ / 256, NTOK / 128), 256, SM_F>>>(
        hbuf, w2c, FQ, t2s, u2t, EKQ, b2m, nullptr, out, HQ);
}

// round 4
// speedup vs baseline: 1.5376x; 1.3790x over previous
#include <cuda_runtime.h>
#include <cstdint>
#include <cstddef>

// ---------------------------------------------------------------------------
// RankOneMoE, legacy tensor path (mma.sync.m16n8k8.tf32; harness PTX target is
// compute_103 without 'a' features, so no tcgen05).
//   gw[b,ek]  = (sum_s relu(x@gw1^T+b1g))[b,:]@gw2[ek,:]^T /512 + b2g[ek]
//   h         = relu([x | (x@SVH1^T)*gw] @ [W1^T ; U1] + b1m)
//   out       = [h | (h@SVH2^T)*gw] @ [W2^T ; U2] + b2m
// Operands pre-rounded to tf32 (rna) in a k-interleaved layout (LDS.128 frags).
// R4: spill-free warp tiles (64x32), launch_bounds-forced 2 CTA/SM, gw fold.
// ---------------------------------------------------------------------------

#define BQ   16
#define SQ   512
#define HQ   768
#define FQ   3072
#define EQ   8
#define EKQ  128
#define G1Q  256
#define NTOK (BQ*SQ)      // 8192
#define LAMBDA 0.2f

// ---- scratch layout (floats) ----
#define OFF_XC    0                         // 8192*768
#define OFF_WG1   6291456                   // 256*768
#define OFF_SVH1  6488064                   // 128*768
#define OFF_W1    6586368                   // 3072*768
#define OFF_U1T   8945664                   // 3072*128
#define OFF_SVH2  9338880                   // 128*3072
#define OFF_W2    9732096                   // 768*3072
#define OFF_U2T   12091392                  // 768*128
#define OFF_G1    12189696                  // 8192*256
#define OFF_B1M   14292992                  // 3072
#define OFF_B2M   14296064                  // 768
#define OFF_T1S   14296832                  // 8192*128
#define OFF_T2S   15345408                  // 8192*128
#define OFF_H     16393984                  // 8192*3072
#define OFF_P8    41559808                  // 16*8*256
#define SCRATCH_FLOATS 41592576

static __device__ __align__(256) float g_scratch[SCRATCH_FLOATS];

// ---------------------------- helpers --------------------------------------
__device__ __forceinline__ float tf32r(float a) {
    float r;
    asm("cvt.rna.tf32.f32 %0, %1;" : "=f"(r) : "f"(a));
    return r;
}
__device__ __forceinline__ uint32_t s2u(const void* p) {
    uint32_t a;
    asm("{ .reg .u64 t; cvta.to.shared.u64 t, %1; cvt.u32.u64 %0, t; }" : "=r"(a) : "l"(p));
    return a;
}
// interleave within 16-col group: c -> (c%4)*4 + c/4   (involution)
__device__ __forceinline__ int ilv16(int c) {
    return (c & ~15) | ((c & 3) << 2) | ((c >> 2) & 3);
}
__device__ __forceinline__ void mma8(float* c,
                                     uint32_t a0, uint32_t a1, uint32_t a2, uint32_t a3,
                                     uint32_t b0, uint32_t b1) {
    asm volatile(
        "mma.sync.aligned.m16n8k8.row.col.f32.tf32.tf32.f32 "
        "{%0,%1,%2,%3},{%4,%5,%6,%7},{%8,%9},{%0,%1,%2,%3};\n"
        : "+f"(c[0]), "+f"(c[1]), "+f"(c[2]), "+f"(c[3])
        : "r"(a0), "r"(a1), "r"(a2), "r"(a3), "r"(b0), "r"(b1));
}

// ---------------------------- pack kernels ---------------------------------
__global__ void k_pack(float* __restrict__ dst, const float* __restrict__ src, int ngroups) {
    int g = blockIdx.x * blockDim.x + threadIdx.x;
    if (g >= ngroups) return;
    const float4* s = reinterpret_cast<const float4*>(src) + (size_t)g * 4;
    float4 v0 = s[0], v1 = s[1], v2 = s[2], v3 = s[3];
    float4* d = reinterpret_cast<float4*>(dst) + (size_t)g * 4;
    d[0] = make_float4(tf32r(v0.x), tf32r(v1.x), tf32r(v2.x), tf32r(v3.x));
    d[1] = make_float4(tf32r(v0.y), tf32r(v1.y), tf32r(v2.y), tf32r(v3.y));
    d[2] = make_float4(tf32r(v0.z), tf32r(v1.z), tf32r(v2.z), tf32r(v3.z));
    d[3] = make_float4(tf32r(v0.w), tf32r(v1.w), tf32r(v2.w), tf32r(v3.w));
}

__global__ void k_tr_ilv(const float* __restrict__ S_, float* __restrict__ Dst, int Ncols) {
    __shared__ float t[32][33];
    const int nx = blockIdx.x * 32, my = blockIdx.y * 32;
    const int x = threadIdx.x, y = threadIdx.y;
    #pragma unroll
    for (int i = 0; i < 32; i += 8)
        t[y + i][x] = S_[(size_t)(my + y + i) * Ncols + nx + x];
    __syncthreads();
    #pragma unroll
    for (int i = 0; i < 32; i += 8)
        Dst[(size_t)(nx + y + i) * 128 + ilv16(my + x)] = tf32r(t[x][y + i]);
}

__global__ void k_prep(const float* __restrict__ b1, const float* __restrict__ tb1,
                       const float* __restrict__ b2, const float* __restrict__ tb2,
                       float* __restrict__ b1m, float* __restrict__ b2m) {
    int i = blockIdx.x * blockDim.x + threadIdx.x;
    if (i < FQ) {
        float s = 0.f;
        #pragma unroll
        for (int e = 0; e < EQ; ++e) s += tb1[e * FQ + i];
        b1m[i] = b1[i] + LAMBDA * s;
    }
    if (i < HQ) {
        float s = 0.f;
        #pragma unroll
        for (int e = 0; e < EQ; ++e) s += tb2[e * HQ + i];
        b2m[i] = b2[i] + LAMBDA * s;
    }
}

// two-level mean reduction over S (level 1)
__global__ void k_sumG1b(const float* __restrict__ G1, float* __restrict__ P8) {
    int b = blockIdx.x, ch = blockIdx.y, g = threadIdx.x;      // 256 threads
    const float* p = G1 + ((size_t)b * SQ + ch * 64) * G1Q + g;
    float a = 0.f;
    #pragma unroll 8
    for (int s = 0; s < 64; ++s) a += p[(size_t)s * G1Q];
    P8[(b * 8 + ch) * G1Q + g] = a;
}

// ---------------------------------------------------------------------------
// Pipelined TF32 mma.sync GEMM on interleaved operands.
//   D[8192,N] = epi( A1[8192,K1] @ B1[N,K1]^T (+ A2[8192,K2] @ B2[N,K2]^T) )
//   4-stage cp.async, BK=16. EPI: 0=none, 1=relu, 2=scale by inline gw.
//   INLINE_GW (only with EPI==2, THREADS==128, BN==128, bN==0): computes
//   gw[b, 0:128] from P8/gate_w2/gate_b2 in-kernel.
// ---------------------------------------------------------------------------
template<int BM, int BN, int WM, int WN, int EPI,
         bool HAS2, bool ROUND, bool HAS_BIAS, bool ILVOUT, bool INLINE_GW>
__global__ void __launch_bounds__(WM * WN * 32, 2)
k_mma(const float* __restrict__ A1, const float* __restrict__ B1, int K1,
      const float* __restrict__ A2, const float* __restrict__ B2, int K2,
      const float* __restrict__ bias,
      const float* __restrict__ P8, const float* __restrict__ w2g,
      const float* __restrict__ gb2,
      float* __restrict__ D, int N)
{
    constexpr int THREADS = WM * WN * 32;
    constexpr int WTM = BM / WM, WTN = BN / WN;
    constexpr int MT = WTM / 16, NT = WTN / 8;
    constexpr int STGF = (BM + BN) * 16;          // floats per stage
    constexpr int AIT = (BM * 4) / THREADS;
    constexpr int BIT = (BN * 4) / THREADS;

    extern __shared__ float sm[];
    const uint32_t smb = s2u(sm);
    float* Ps  = sm + 4 * STGF;                   // [256] (INLINE_GW only)
    float* gws = Ps + G1Q;                        // [128]

    const int tid = threadIdx.x;
    const int wid = tid >> 5, lane = tid & 31;
    const int gid = lane >> 2, tig = lane & 3;
    const int wm = (wid / WN) * WTM;
    const int wn = (wid % WN) * WTN;
    const int bM = blockIdx.y * BM;
    const int bN = blockIdx.x * BN;
    const int T1 = K1 >> 4;
    const int T  = T1 + (HAS2 ? (K2 >> 4) : 0);

    float acc[MT][NT][4];
    #pragma unroll
    for (int mi = 0; mi < MT; ++mi)
        #pragma unroll
        for (int ni = 0; ni < NT; ++ni)
            #pragma unroll
            for (int j = 0; j < 4; ++j) acc[mi][ni][j] = 0.f;

    auto issue = [&](int jj) {
        const float* a; const float* b; int lda, ldb, k0;
        if (!HAS2 || jj < T1) { a = A1; lda = K1; b = B1; ldb = K1; k0 = jj << 4; }
        else                  { a = A2; lda = K2; b = B2; ldb = K2; k0 = (jj - T1) << 4; }
        const uint32_t sA = smb + (uint32_t)((jj & 3) * STGF) * 4u;
        const uint32_t sB = sA + (uint32_t)BM * 64u;
        #pragma unroll
        for (int i = 0; i < AIT; ++i) {
            int idx = tid + i * THREADS; int r = idx >> 2, c = idx & 3;
            const float* src = a + (size_t)(bM + r) * lda + k0 + c * 4;
            asm volatile("cp.async.cg.shared.global [%0], [%1], 16;\n"
                         :: "r"(sA + (uint32_t)(r * 64 + c * 16)), "l"(src) : "memory");
        }
        #pragma unroll
        for (int i = 0; i < BIT; ++i) {
            int idx = tid + i * THREADS; int r = idx >> 2, c = idx & 3;
            const float* src = b + (size_t)(bN + r) * ldb + k0 + c * 4;
            asm volatile("cp.async.cg.shared.global [%0], [%1], 16;\n"
                         :: "r"(sB + (uint32_t)(r * 64 + c * 16)), "l"(src) : "memory");
        }
    };

    issue(0); asm volatile("cp.async.commit_group;\n" ::: "memory");
    issue(1); asm volatile("cp.async.commit_group;\n" ::: "memory");
    issue(2); asm volatile("cp.async.commit_group;\n" ::: "memory");

    if (INLINE_GW) {
        // gw[b, c] = dot(P[b,:], w2[c,:]) / 512 + gb2[c], b = bM>>9 (128 thr)
        const int b = bM >> 9;
        #pragma unroll
        for (int half = 0; half < 2; ++half) {
            const int g = tid + half * 128;
            float a = 0.f;
            #pragma unroll
            for (int ch = 0; ch < 8; ++ch) a += P8[(b * 8 + ch) * G1Q + g];
            Ps[g] = a;
        }
        __syncthreads();
        const float* w = w2g + (size_t)tid * G1Q;
        float a = 0.f;
        #pragma unroll 8
        for (int g = 0; g < G1Q; ++g) a += w[g] * Ps[g];
        gws[tid] = a * (1.0f / (float)SQ) + gb2[tid];
    }

    for (int j = 0; j < T; ++j) {
        asm volatile("cp.async.wait_group 2;\n" ::: "memory");
        __syncthreads();

        const float* sA = sm + (j & 3) * STGF;
        const float* sB = sA + BM * 16;

        float4 fb[NT];
        #pragma unroll
        for (int ni = 0; ni < NT; ++ni) {
            const int c = wn + ni * 8 + gid;
            fb[ni] = *reinterpret_cast<const float4*>(sB + c * 16 + tig * 4);
        }

        if (j + 3 < T) issue(j + 3);
        asm volatile("cp.async.commit_group;\n" ::: "memory");

        #pragma unroll
        for (int mi = 0; mi < MT; ++mi) {
            const int r = wm + mi * 16 + gid;
            const float4 fa0 = *reinterpret_cast<const float4*>(sA + r * 16 + tig * 4);
            const float4 fa1 = *reinterpret_cast<const float4*>(sA + (r + 8) * 16 + tig * 4);
            #pragma unroll
            for (int ni = 0; ni < NT; ++ni)
                mma8(acc[mi][ni],
                     __float_as_uint(fa0.x), __float_as_uint(fa1.x),
                     __float_as_uint(fa0.y), __float_as_uint(fa1.y),
                     __float_as_uint(fb[ni].x), __float_as_uint(fb[ni].y));
            #pragma unroll
            for (int ni = 0; ni < NT; ++ni)
                mma8(acc[mi][ni],
                     __float_as_uint(fa0.z), __float_as_uint(fa1.z),
                     __float_as_uint(fa0.w), __float_as_uint(fa1.w),
                     __float_as_uint(fb[ni].z), __float_as_uint(fb[ni].w));
        }
    }

    if (INLINE_GW) __syncthreads();   // gws visible (redundant w/ loop syncs, cheap)

    // epilogue
    #pragma unroll
    for (int mi = 0; mi < MT; ++mi) {
        const int r0 = bM + wm + mi * 16 + gid;
        #pragma unroll
        for (int ni = 0; ni < NT; ++ni) {
            const int cl = wn + ni * 8 + tig * 2;
            const int c  = bN + cl;
            const float bb0 = HAS_BIAS ? bias[c] : 0.f;
            const float bb1 = HAS_BIAS ? bias[c + 1] : 0.f;
            #pragma unroll
            for (int h = 0; h < 2; ++h) {
                const int r = r0 + h * 8;
                float v0 = acc[mi][ni][2 * h + 0] + bb0;
                float v1 = acc[mi][ni][2 * h + 1] + bb1;
                if (EPI == 1) { v0 = fmaxf(v0, 0.f); v1 = fmaxf(v1, 0.f); }
                if (EPI == 2) { v0 *= gws[cl]; v1 *= gws[cl + 1]; }
                if (ROUND) { v0 = tf32r(v0); v1 = tf32r(v1); }
                if (ILVOUT) {
                    D[(size_t)r * N + ilv16(c)]     = v0;
                    D[(size_t)r * N + ilv16(c + 1)] = v1;
                } else {
                    *reinterpret_cast<float2*>(D + (size_t)r * N + c) = make_float2(v0, v1);
                }
            }
        }
    }
}

// ---------------------------------------------------------------------------
extern "C" void kernel_launch(void* const* d_in, const int* in_sizes, int n_in,
                              void* d_out, int out_size) {
    const float* x       = (const float*)d_in[0];
    const float* gate_w1 = (const float*)d_in[1];
    const float* gate_b1 = (const float*)d_in[2];
    const float* gate_w2 = (const float*)d_in[3];
    const float* gate_b2 = (const float*)d_in[4];
    const float* W1      = (const float*)d_in[5];
    const float* b1      = (const float*)d_in[6];
    const float* W2      = (const float*)d_in[7];
    const float* b2      = (const float*)d_in[8];
    const float* U1      = (const float*)d_in[9];
    const float* SVH1    = (const float*)d_in[10];
    const float* U2      = (const float*)d_in[11];
    const float* SVH2    = (const float*)d_in[12];
    const float* TB1     = (const float*)d_in[13];
    const float* TB2     = (const float*)d_in[14];
    float* out = (float*)d_out;

    float* S = nullptr;
    cudaGetSymbolAddress((void**)&S, g_scratch);
    float* xc    = S + OFF_XC;
    float* wg1c  = S + OFF_WG1;
    float* svh1c = S + OFF_SVH1;
    float* w1c   = S + OFF_W1;
    float* u1t   = S + OFF_U1T;
    float* svh2c = S + OFF_SVH2;
    float* w2c   = S + OFF_W2;
    float* u2t   = S + OFF_U2T;
    float* G1    = S + OFF_G1;
    float* b1m   = S + OFF_B1M;
    float* b2m   = S + OFF_B2M;
    float* t1s   = S + OFF_T1S;
    float* t2s   = S + OFF_T2S;
    float* hbuf  = S + OFF_H;
    float* P8    = S + OFF_P8;

    // router: BM64 BN256, 8 warps (1x8), warp tile 64x32
    auto kr = k_mma<64, 256, 1, 8, 1, false, false, true, false, false>;
    // t-GEMMs: BM64 BN128, 4 warps (2x2), warp tile 32x64, inline gw
    auto kt = k_mma<64, 128, 2, 2, 2, false, true, false, true, true>;
    // fc1: BM128 BN128, 8 warps (2x4), warp tile 64x32
    auto k1 = k_mma<128, 128, 2, 4, 1, true, true, true, true, false>;
    // fc2: same tiles, plain epilogue
    auto k2 = k_mma<128, 128, 2, 4, 0, true, false, true, false, false>;

    const int SM_R = 4 * (64 + 256) * 16 * 4;                 // 81920
    const int SM_T = 4 * (64 + 128) * 16 * 4 + (256 + 128) * 4; // 50688
    const int SM_F = 4 * (128 + 128) * 16 * 4;                // 65536
    cudaFuncSetAttribute((const void*)kr, cudaFuncAttributeMaxDynamicSharedMemorySize, SM_R);
    cudaFuncSetAttribute((const void*)kt, cudaFuncAttributeMaxDynamicSharedMemorySize, SM_T);
    cudaFuncSetAttribute((const void*)k1, cudaFuncAttributeMaxDynamicSharedMemorySize, SM_F);
    cudaFuncSetAttribute((const void*)k2, cudaFuncAttributeMaxDynamicSharedMemorySize, SM_F);

    // launches ordered so ncu (-s 5 -c 1) captures launch #5 = kt (t1s GEMM)
    k_pack<<<(NTOK * HQ / 16 + 255) / 256, 256>>>(xc,    x,       NTOK * HQ / 16);   // 0
    k_pack<<<(G1Q * HQ / 16 + 255) / 256, 256>>>(wg1c,  gate_w1, G1Q * HQ / 16);     // 1
    k_pack<<<(EKQ * HQ / 16 + 255) / 256, 256>>>(svh1c, SVH1,    EKQ * HQ / 16);     // 2

    // 3: router G1 = relu(x @ gate_w1^T + gate_b1)   [8192,256]
    kr<<<dim3(1, NTOK / 64), 256, SM_R>>>(
        xc, wg1c, HQ, nullptr, nullptr, 0, gate_b1, nullptr, nullptr, nullptr, G1, G1Q);

    // 4: partial sums over S
    k_sumG1b<<<dim3(BQ, 8), 256>>>(G1, P8);

    // 5: t1s = round((x @ SVH1^T) * gw)  [8192,128] ILV   (gw inline)  << profiled
    kt<<<dim3(1, NTOK / 64), 128, SM_T>>>(
        xc, svh1c, HQ, nullptr, nullptr, 0, nullptr, P8, gate_w2, gate_b2, t1s, EKQ);

    k_pack<<<(FQ * HQ / 16 + 255) / 256, 256>>>(w1c, W1, FQ * HQ / 16);              // 6
    k_tr_ilv<<<dim3(FQ / 32, 4), dim3(32, 8)>>>(U1, u1t, FQ);                        // 7
    k_prep<<<(FQ + 255) / 256, 256>>>(b1, TB1, b2, TB2, b1m, b2m);                   // 8

    // 9: h = round(relu(x @ W1^T + t1s @ U1 + b1m))   [8192,3072] ILV
    k1<<<dim3(FQ / 128, NTOK / 128), 256, SM_F>>>(
        xc, w1c, HQ, t1s, u1t, EKQ, b1m, nullptr, nullptr, nullptr, hbuf, FQ);

    k_pack<<<(EKQ * FQ / 16 + 255) / 256, 256>>>(svh2c, SVH2, EKQ * FQ / 16);        // 10

    // 11: t2s = round((h @ SVH2^T) * gw)   [8192,128] ILV
    kt<<<dim3(1, NTOK / 64), 128, SM_T>>>(
        hbuf, svh2c, FQ, nullptr, nullptr, 0, nullptr, P8, gate_w2, gate_b2, t2s, EKQ);

    k_pack<<<(HQ * FQ / 16 + 255) / 256, 256>>>(w2c, W2, HQ * FQ / 16);              // 12
    k_tr_ilv<<<dim3(HQ / 32, 4), dim3(32, 8)>>>(U2, u2t, HQ);                        // 13

    // 14: out = h @ W2^T + t2s @ U2 + b2m   [8192,768]
    k2<<<dim3(HQ / 128, NTOK / 128), 256, SM_F>>>(
        hbuf, w2c, FQ, t2s, u2t, EKQ, b2m, nullptr, nullptr, nullptr, out, HQ);
}

// round 5
// speedup vs baseline: 1.5682x; 1.0199x over previous
#include <cuda_runtime.h>
#include <cstdint>
#include <cstddef>

// ---------------------------------------------------------------------------
// RankOneMoE, legacy tensor path (mma.sync.m16n8k8.tf32; harness PTX target is
// compute_103 without 'a' features, so no tcgen05).
//   gw[b,ek]  = (sum_s relu(x@gw1^T+b1g))[b,:]@gw2[ek,:]^T /512 + b2g[ek]
//   h         = relu([x | (x@SVH1^T)*gw] @ [W1^T ; U1] + b1m)
//   out       = [h | (h@SVH2^T)*gw] @ [W2^T ; U2] + b2m
// Operands pre-rounded to tf32 (rna), k-interleaved (LDS.128 frags).
// R5: BK32 stages (half the barriers), 2 CTA/SM residency, t2 split-K,
//     fused packs.
// ---------------------------------------------------------------------------

#define BQ   16
#define SQ   512
#define HQ   768
#define FQ   3072
#define EQ   8
#define EKQ  128
#define G1Q  256
#define NTOK (BQ*SQ)      // 8192
#define LAMBDA 0.2f
#define KSPLIT 4

// ---- scratch layout (floats) ----
#define OFF_XC    0                         // 8192*768
#define OFF_WG1   6291456                   // 256*768
#define OFF_SVH1  6488064                   // 128*768
#define OFF_W1    6586368                   // 3072*768
#define OFF_U1T   8945664                   // 3072*128
#define OFF_SVH2  9338880                   // 128*3072
#define OFF_W2    9732096                   // 768*3072
#define OFF_U2T   12091392                  // 768*128
#define OFF_G1    12189696                  // 8192*256
#define OFF_B1M   14292992                  // 3072
#define OFF_B2M   14296064                  // 768
#define OFF_T1S   14296832                  // 8192*128
#define OFF_T2S   15345408                  // 8192*128
#define OFF_H     16393984                  // 8192*3072
#define OFF_P8    41559808                  // 16*8*256
#define OFF_T2P   41592576                  // 4*8192*128
#define OFF_GWV   45786880                  // 16*128
#define SCRATCH_FLOATS 45788928

static __device__ __align__(256) float g_scratch[SCRATCH_FLOATS];

// ---------------------------- helpers --------------------------------------
__device__ __forceinline__ float tf32r(float a) {
    float r;
    asm("cvt.rna.tf32.f32 %0, %1;" : "=f"(r) : "f"(a));
    return r;
}
__device__ __forceinline__ uint32_t s2u(const void* p) {
    uint32_t a;
    asm("{ .reg .u64 t; cvta.to.shared.u64 t, %1; cvt.u32.u64 %0, t; }" : "=r"(a) : "l"(p));
    return a;
}
// interleave within 16-col group: c -> (c%4)*4 + c/4   (involution)
__device__ __forceinline__ int ilv16(int c) {
    return (c & ~15) | ((c & 3) << 2) | ((c >> 2) & 3);
}
__device__ __forceinline__ void mma8(float* c,
                                     uint32_t a0, uint32_t a1, uint32_t a2, uint32_t a3,
                                     uint32_t b0, uint32_t b1) {
    asm volatile(
        "mma.sync.aligned.m16n8k8.row.col.f32.tf32.tf32.f32 "
        "{%0,%1,%2,%3},{%4,%5,%6,%7},{%8,%9},{%0,%1,%2,%3};\n"
        : "+f"(c[0]), "+f"(c[1]), "+f"(c[2]), "+f"(c[3])
        : "r"(a0), "r"(a1), "r"(a2), "r"(a3), "r"(b0), "r"(b1));
}

// ---------------------------- pack kernels ---------------------------------
struct PackJobs {
    const float* src[6];
    float*       dst[6];
    int          ngroups[6];
};

__global__ void k_pack6(PackJobs J) {
    const int job = blockIdx.y;
    const int g = blockIdx.x * blockDim.x + threadIdx.x;
    if (g >= J.ngroups[job]) return;
    const float4* s = reinterpret_cast<const float4*>(J.src[job]) + (size_t)g * 4;
    float4 v0 = s[0], v1 = s[1], v2 = s[2], v3 = s[3];
    float4* d = reinterpret_cast<float4*>(J.dst[job]) + (size_t)g * 4;
    d[0] = make_float4(tf32r(v0.x), tf32r(v1.x), tf32r(v2.x), tf32r(v3.x));
    d[1] = make_float4(tf32r(v0.y), tf32r(v1.y), tf32r(v2.y), tf32r(v3.y));
    d[2] = make_float4(tf32r(v0.z), tf32r(v1.z), tf32r(v2.z), tf32r(v3.z));
    d[3] = make_float4(tf32r(v0.w), tf32r(v1.w), tf32r(v2.w), tf32r(v3.w));
}

__global__ void k_tr_ilv(const float* __restrict__ S_, float* __restrict__ Dst, int Ncols) {
    __shared__ float t[32][33];
    const int nx = blockIdx.x * 32, my = blockIdx.y * 32;
    const int x = threadIdx.x, y = threadIdx.y;
    #pragma unroll
    for (int i = 0; i < 32; i += 8)
        t[y + i][x] = S_[(size_t)(my + y + i) * Ncols + nx + x];
    __syncthreads();
    #pragma unroll
    for (int i = 0; i < 32; i += 8)
        Dst[(size_t)(nx + y + i) * 128 + ilv16(my + x)] = tf32r(t[x][y + i]);
}

__global__ void k_prep(const float* __restrict__ b1, const float* __restrict__ tb1,
                       const float* __restrict__ b2, const float* __restrict__ tb2,
                       float* __restrict__ b1m, float* __restrict__ b2m) {
    int i = blockIdx.x * blockDim.x + threadIdx.x;
    if (i < FQ) {
        float s = 0.f;
        #pragma unroll
        for (int e = 0; e < EQ; ++e) s += tb1[e * FQ + i];
        b1m[i] = b1[i] + LAMBDA * s;
    }
    if (i < HQ) {
        float s = 0.f;
        #pragma unroll
        for (int e = 0; e < EQ; ++e) s += tb2[e * HQ + i];
        b2m[i] = b2[i] + LAMBDA * s;
    }
}

// two-level mean reduction over S (level 1)
__global__ void k_sumG1b(const float* __restrict__ G1, float* __restrict__ P8) {
    int b = blockIdx.x, ch = blockIdx.y, g = threadIdx.x;      // 256 threads
    const float* p = G1 + ((size_t)b * SQ + ch * 64) * G1Q + g;
    float a = 0.f;
    #pragma unroll 8
    for (int s = 0; s < 64; ++s) a += p[(size_t)s * G1Q];
    P8[(b * 8 + ch) * G1Q + g] = a;
}

// t2 split-K reduce: sum 4 partials, scale by gw, round, interleave
__global__ void k_red(const float* __restrict__ t2p, const float* __restrict__ gwv,
                      float* __restrict__ t2s) {
    const int i = blockIdx.x * 256 + threadIdx.x;   // over 8192*128
    const int r = i >> 7, c = i & 127;
    float v = t2p[i];
    #pragma unroll
    for (int z = 1; z < KSPLIT; ++z) v += t2p[i + (size_t)z * NTOK * EKQ];
    t2s[((size_t)r << 7) + ilv16(c)] = tf32r(v * gwv[((r >> 9) << 7) + c]);
}

// ---------------------------------------------------------------------------
// Pipelined TF32 mma.sync GEMM on interleaved operands. BK=32 per stage,
// 3 stages, 2-deep prefetch, one barrier per 32 k.
//   D[8192,N] = epi( A1[8192,K1] @ B1[N,K1]^T (+ A2[8192,K2] @ B2[N,K2]^T) )
//   EPI: 0=none, 1=relu, 2=scale by inline gw (gws in smem).
//   SPLITK: blockIdx.z selects a kspan-wide K window of A1/B1; D offset by z.
// ---------------------------------------------------------------------------
template<int BM, int BN, int WM, int WN, int EPI,
         bool HAS2, bool ROUND, bool HAS_BIAS, bool ILVOUT, bool INLINE_GW, bool SPLITK>
__global__ void __launch_bounds__(WM * WN * 32, 2)
k_mma(const float* __restrict__ A1, const float* __restrict__ B1, int K1,
      const float* __restrict__ A2, const float* __restrict__ B2, int K2,
      const float* __restrict__ bias,
      const float* __restrict__ P8, const float* __restrict__ w2g,
      const float* __restrict__ gb2, float* __restrict__ gwout,
      float* __restrict__ D, int N, int kspan)
{
    constexpr int THREADS = WM * WN * 32;
    constexpr int WTM = BM / WM, WTN = BN / WN;
    constexpr int MT = WTM / 16, NT = WTN / 8;
    constexpr int STGF = (BM + BN) * 32;          // floats per stage
    constexpr int AIT = (BM * 8) / THREADS;       // 16B chunks per thread (A)
    constexpr int BIT = (BN * 8) / THREADS;

    extern __shared__ float sm[];
    const uint32_t smb = s2u(sm);
    float* Ps  = sm + 3 * STGF;                   // [256] (INLINE_GW only)
    float* gws = Ps + G1Q;                        // [128]

    const int tid = threadIdx.x;
    const int wid = tid >> 5, lane = tid & 31;
    const int gid = lane >> 2, tig = lane & 3;
    const int wm = (wid / WN) * WTM;
    const int wn = (wid % WN) * WTN;
    const int bM = blockIdx.y * BM;
    const int bN = blockIdx.x * BN;
    const int kbase = SPLITK ? blockIdx.z * kspan : 0;
    const int T1S = SPLITK ? (kspan >> 5) : (K1 >> 5);
    const int TS  = T1S + (HAS2 ? (K2 >> 5) : 0);

    float* Dp = SPLITK ? (D + (size_t)blockIdx.z * NTOK * N) : D;

    float acc[MT][NT][4];
    #pragma unroll
    for (int mi = 0; mi < MT; ++mi)
        #pragma unroll
        for (int ni = 0; ni < NT; ++ni)
            #pragma unroll
            for (int j = 0; j < 4; ++j) acc[mi][ni][j] = 0.f;

    auto issue = [&](int jj) {
        const float* a; const float* b; int lda, ldb, k0;
        if (!HAS2 || jj < T1S) { a = A1; lda = K1; b = B1; ldb = K1; k0 = kbase + (jj << 5); }
        else                   { a = A2; lda = K2; b = B2; ldb = K2; k0 = (jj - T1S) << 5; }
        const uint32_t sA = smb + (uint32_t)((jj % 3) * STGF) * 4u;
        const uint32_t sB = sA + (uint32_t)BM * 128u;
        #pragma unroll
        for (int i = 0; i < AIT; ++i) {
            int idx = tid + i * THREADS;
            int r = idx >> 3, c = idx & 7, hf = c >> 2, cc = c & 3;
            const float* src = a + (size_t)(bM + r) * lda + k0 + hf * 16 + cc * 4;
            asm volatile("cp.async.cg.shared.global [%0], [%1], 16;\n"
                         :: "r"(sA + (uint32_t)(hf * BM * 64 + r * 64 + cc * 16)),
                            "l"(src) : "memory");
        }
        #pragma unroll
        for (int i = 0; i < BIT; ++i) {
            int idx = tid + i * THREADS;
            int r = idx >> 3, c = idx & 7, hf = c >> 2, cc = c & 3;
            const float* src = b + (size_t)(bN + r) * ldb + k0 + hf * 16 + cc * 4;
            asm volatile("cp.async.cg.shared.global [%0], [%1], 16;\n"
                         :: "r"(sB + (uint32_t)(hf * BN * 64 + r * 64 + cc * 16)),
                            "l"(src) : "memory");
        }
    };

    issue(0); asm volatile("cp.async.commit_group;\n" ::: "memory");
    issue(1); asm volatile("cp.async.commit_group;\n" ::: "memory");

    if (INLINE_GW) {
        // gw[b, c] = dot(P[b,:], w2[c,:]) / 512 + gb2[c];  b = bM>>9
        const int b = bM >> 9;
        float a = 0.f;
        #pragma unroll
        for (int ch = 0; ch < 8; ++ch) a += P8[(b * 8 + ch) * G1Q + tid];
        Ps[tid] = a;                                 // THREADS == 256 == G1Q
        __syncthreads();
        if (tid < EKQ) {
            const float* w = w2g + (size_t)tid * G1Q;
            float s = 0.f;
            #pragma unroll 8
            for (int g = 0; g < G1Q; ++g) s += w[g] * Ps[g];
            s = s * (1.0f / (float)SQ) + gb2[tid];
            gws[tid] = s;
            gwout[b * EKQ + tid] = s;                // duplicate writes OK
        }
    }

    for (int j = 0; j < TS; ++j) {
        asm volatile("cp.async.wait_group 1;\n" ::: "memory");
        __syncthreads();

        const float* sA = sm + (j % 3) * STGF;
        const float* sB = sA + BM * 32;

        // ---- k16 half 0 ----
        float4 fb[NT];
        #pragma unroll
        for (int ni = 0; ni < NT; ++ni) {
            const int c = wn + ni * 8 + gid;
            fb[ni] = *reinterpret_cast<const float4*>(sA + 2 * BM * 16 + c * 16 + tig * 4);
        }

        if (j + 2 < TS) issue(j + 2);                // refills slot (j-1)%3
        asm volatile("cp.async.commit_group;\n" ::: "memory");

        #pragma unroll
        for (int mi = 0; mi < MT; ++mi) {
            const int r = wm + mi * 16 + gid;
            const float4 fa0 = *reinterpret_cast<const float4*>(sA + r * 16 + tig * 4);
            const float4 fa1 = *reinterpret_cast<const float4*>(sA + (r + 8) * 16 + tig * 4);
            #pragma unroll
            for (int ni = 0; ni < NT; ++ni)
                mma8(acc[mi][ni],
                     __float_as_uint(fa0.x), __float_as_uint(fa1.x),
                     __float_as_uint(fa0.y), __float_as_uint(fa1.y),
                     __float_as_uint(fb[ni].x), __float_as_uint(fb[ni].y));
            #pragma unroll
            for (int ni = 0; ni < NT; ++ni)
                mma8(acc[mi][ni],
                     __float_as_uint(fa0.z), __float_as_uint(fa1.z),
                     __float_as_uint(fa0.w), __float_as_uint(fa1.w),
                     __float_as_uint(fb[ni].z), __float_as_uint(fb[ni].w));
        }

        // ---- k16 half 1 ----
        const float* sA1 = sA + BM * 16;
        const float* sB1 = sA + 2 * BM * 16 + BN * 16;
        #pragma unroll
        for (int ni = 0; ni < NT; ++ni) {
            const int c = wn + ni * 8 + gid;
            fb[ni] = *reinterpret_cast<const float4*>(sB1 + c * 16 + tig * 4);
        }
        #pragma unroll
        for (int mi = 0; mi < MT; ++mi) {
            const int r = wm + mi * 16 + gid;
            const float4 fa0 = *reinterpret_cast<const float4*>(sA1 + r * 16 + tig * 4);
            const float4 fa1 = *reinterpret_cast<const float4*>(sA1 + (r + 8) * 16 + tig * 4);
            #pragma unroll
            for (int ni = 0; ni < NT; ++ni)
                mma8(acc[mi][ni],
                     __float_as_uint(fa0.x), __float_as_uint(fa1.x),
                     __float_as_uint(fa0.y), __float_as_uint(fa1.y),
                     __float_as_uint(fb[ni].x), __float_as_uint(fb[ni].y));
            #pragma unroll
            for (int ni = 0; ni < NT; ++ni)
                mma8(acc[mi][ni],
                     __float_as_uint(fa0.z), __float_as_uint(fa1.z),
                     __float_as_uint(fa0.w), __float_as_uint(fa1.w),
                     __float_as_uint(fb[ni].z), __float_as_uint(fb[ni].w));
        }
    }

    // epilogue
    #pragma unroll
    for (int mi = 0; mi < MT; ++mi) {
        const int r0 = bM + wm + mi * 16 + gid;
        #pragma unroll
        for (int ni = 0; ni < NT; ++ni) {
            const int cl = wn + ni * 8 + tig * 2;
            const int c  = bN + cl;
            const float bb0 = HAS_BIAS ? bias[c] : 0.f;
            const float bb1 = HAS_BIAS ? bias[c + 1] : 0.f;
            #pragma unroll
            for (int h = 0; h < 2; ++h) {
                const int r = r0 + h * 8;
                float v0 = acc[mi][ni][2 * h + 0] + bb0;
                float v1 = acc[mi][ni][2 * h + 1] + bb1;
                if (EPI == 1) { v0 = fmaxf(v0, 0.f); v1 = fmaxf(v1, 0.f); }
                if (EPI == 2) { v0 *= gws[cl]; v1 *= gws[cl + 1]; }
                if (ROUND) { v0 = tf32r(v0); v1 = tf32r(v1); }
                if (ILVOUT) {
                    Dp[(size_t)r * N + ilv16(c)]     = v0;
                    Dp[(size_t)r * N + ilv16(c + 1)] = v1;
                } else {
                    *reinterpret_cast<float2*>(Dp + (size_t)r * N + c) = make_float2(v0, v1);
                }
            }
        }
    }
}

// ---------------------------------------------------------------------------
extern "C" void kernel_launch(void* const* d_in, const int* in_sizes, int n_in,
                              void* d_out, int out_size) {
    const float* x       = (const float*)d_in[0];
    const float* gate_w1 = (const float*)d_in[1];
    const float* gate_b1 = (const float*)d_in[2];
    const float* gate_w2 = (const float*)d_in[3];
    const float* gate_b2 = (const float*)d_in[4];
    const float* W1      = (const float*)d_in[5];
    const float* b1      = (const float*)d_in[6];
    const float* W2      = (const float*)d_in[7];
    const float* b2      = (const float*)d_in[8];
    const float* U1      = (const float*)d_in[9];
    const float* SVH1    = (const float*)d_in[10];
    const float* U2      = (const float*)d_in[11];
    const float* SVH2    = (const float*)d_in[12];
    const float* TB1     = (const float*)d_in[13];
    const float* TB2     = (const float*)d_in[14];
    float* out = (float*)d_out;

    float* S = nullptr;
    cudaGetSymbolAddress((void**)&S, g_scratch);
    float* xc    = S + OFF_XC;
    float* wg1c  = S + OFF_WG1;
    float* svh1c = S + OFF_SVH1;
    float* w1c   = S + OFF_W1;
    float* u1t   = S + OFF_U1T;
    float* svh2c = S + OFF_SVH2;
    float* w2c   = S + OFF_W2;
    float* u2t   = S + OFF_U2T;
    float* G1    = S + OFF_G1;
    float* b1m   = S + OFF_B1M;
    float* b2m   = S + OFF_B2M;
    float* t1s   = S + OFF_T1S;
    float* t2s   = S + OFF_T2S;
    float* hbuf  = S + OFF_H;
    float* P8    = S + OFF_P8;
    float* t2p   = S + OFF_T2P;
    float* gwv   = S + OFF_GWV;

    // router: BM64 BN128, 8 warps (2x4), warp 32x32
    auto kr = k_mma<64, 128, 2, 4, 1, false, false, true, false, false, false>;
    // t1: BM64 BN128, 8 warps, inline gw, ILV out
    auto kt1 = k_mma<64, 128, 2, 4, 2, false, true, false, true, true, false>;
    // t2 partial: split-K, raw out
    auto kt2 = k_mma<64, 128, 2, 4, 0, false, false, false, false, false, true>;
    // fc1: BM128 BN128, 8 warps (2x4), warp 64x32
    auto k1 = k_mma<128, 128, 2, 4, 1, true, true, true, true, false, false>;
    // fc2: same tiles, plain epilogue
    auto k2 = k_mma<128, 128, 2, 4, 0, true, false, true, false, false, false>;

    const int SM_RT = 3 * (64 + 128) * 32 * 4 + (G1Q + EKQ) * 4;   // 75264
    const int SM_F  = 3 * (128 + 128) * 32 * 4;                    // 98304
    cudaFuncSetAttribute((const void*)kr,  cudaFuncAttributeMaxDynamicSharedMemorySize, SM_RT);
    cudaFuncSetAttribute((const void*)kt1, cudaFuncAttributeMaxDynamicSharedMemorySize, SM_RT);
    cudaFuncSetAttribute((const void*)kt2, cudaFuncAttributeMaxDynamicSharedMemorySize, SM_RT);
    cudaFuncSetAttribute((const void*)k1,  cudaFuncAttributeMaxDynamicSharedMemorySize, SM_F);
    cudaFuncSetAttribute((const void*)k2,  cudaFuncAttributeMaxDynamicSharedMemorySize, SM_F);

    // 0: all rounds+interleaves in one launch
    PackJobs J;
    J.src[0] = x;       J.dst[0] = xc;    J.ngroups[0] = NTOK * HQ / 16;
    J.src[1] = gate_w1; J.dst[1] = wg1c;  J.ngroups[1] = G1Q * HQ / 16;
    J.src[2] = SVH1;    J.dst[2] = svh1c; J.ngroups[2] = EKQ * HQ / 16;
    J.src[3] = W1;      J.dst[3] = w1c;   J.ngroups[3] = FQ * HQ / 16;
    J.src[4] = SVH2;    J.dst[4] = svh2c; J.ngroups[4] = EKQ * FQ / 16;
    J.src[5] = W2;      J.dst[5] = w2c;   J.ngroups[5] = HQ * FQ / 16;
    k_pack6<<<dim3((NTOK * HQ / 16 + 255) / 256, 6), 256>>>(J);

    // 1,2: transposed low-rank factors
    k_tr_ilv<<<dim3(FQ / 32, 4), dim3(32, 8)>>>(U1, u1t, FQ);
    k_tr_ilv<<<dim3(HQ / 32, 4), dim3(32, 8)>>>(U2, u2t, HQ);

    // 3: router G1 = relu(x @ gate_w1^T + gate_b1)   [8192,256]
    kr<<<dim3(G1Q / 128, NTOK / 64), 256, SM_RT>>>(
        xc, wg1c, HQ, nullptr, nullptr, 0, gate_b1,
        nullptr, nullptr, nullptr, nullptr, G1, G1Q, 0);

    // 4: merged biases
    k_prep<<<(FQ + 255) / 256, 256>>>(b1, TB1, b2, TB2, b1m, b2m);

    // 5: partial sums over S
    k_sumG1b<<<dim3(BQ, 8), 256>>>(G1, P8);

    // 6: t1s = round((x @ SVH1^T) * gw)  [8192,128] ILV  (gw inline, persisted)
    kt1<<<dim3(1, NTOK / 64), 256, SM_RT>>>(
        xc, svh1c, HQ, nullptr, nullptr, 0, nullptr,
        P8, gate_w2, gate_b2, gwv, t1s, EKQ, 0);

    // 7: h = round(relu(x @ W1^T + t1s @ U1 + b1m))   [8192,3072] ILV
    k1<<<dim3(FQ / 128, NTOK / 128), 256, SM_F>>>(
        xc, w1c, HQ, t1s, u1t, EKQ, b1m,
        nullptr, nullptr, nullptr, nullptr, hbuf, FQ, 0);

    // 8: t2 partials = h @ SVH2^T, K split 4x768
    kt2<<<dim3(1, NTOK / 64, KSPLIT), 256, SM_RT>>>(
        hbuf, svh2c, FQ, nullptr, nullptr, 0, nullptr,
        nullptr, nullptr, nullptr, nullptr, t2p, EKQ, FQ / KSPLIT);

    // 9: t2s = round(sum_z t2p * gw)  ILV
    k_red<<<NTOK * EKQ / 256, 256>>>(t2p, gwv, t2s);

    // 10: out = h @ W2^T + t2s @ U2 + b2m   [8192,768]
    k2<<<dim3(HQ / 128, NTOK / 128), 256, SM_F>>>(
        hbuf, w2c, FQ, t2s, u2t, EKQ, b2m,
        nullptr, nullptr, nullptr, nullptr, out, HQ, 0);
}